// round 1
// baseline (speedup 1.0000x reference)
#include <cuda_runtime.h>

// ---------------------------------------------------------------------------
// SLUGenNet GCN: h = relu(An @ (emb@W1+b1)); h2 = relu(An @ (h@W2+b2))
// An = D^-1/2 A D^-1/2, A = self-loops + parent->child (2N-1 nnz, directed).
//
// Key transforms vs reference:
//  1. Sparse aggregation (CSR) instead of dense N x N matmul.
//  2. emb@W1 done on the V=1000 vocab table once (gather commutes with GEMM):
//       P = embed_table @ W1 + b1   [V,32]
//       X1[i] = P[node_ids[i]]
//  3. Layer-2 feature GEMM (32x32) fused into SpMM1 epilogue via warp
//     shuffles: h row lives in registers (lane = feature column).
//
// Inputs (metadata order): node_ids[N] i32, edges[2N-1,2] i32,
//   embed_table[V,256] f32, W1[256,32] f32, b1[32] f32, W2[32,32] f32, b2[32] f32
// Output: [N,32] f32
// ---------------------------------------------------------------------------

#define N_NODES 12288
#define VOCAB   1000
#define EMBD    256
#define FEAT    32
#define NEDGE   (2 * N_NODES - 1)

// Scratch (allocation-free rule: __device__ globals)
__device__ int   g_deg[N_NODES];
__device__ int   g_off[N_NODES + 1];
__device__ int   g_pos[N_NODES];
__device__ int   g_col[NEDGE];
__device__ float g_dinv[N_NODES];
__device__ float g_P[VOCAB * FEAT];        // embed_table@W1 + b1
__device__ float g_X2[N_NODES * FEAT];     // h@W2 + b2 (pre-aggregation)

// ---------------------------------------------------------------- degree ---
__global__ void k_zero_deg() {
    int i = blockIdx.x * blockDim.x + threadIdx.x;
    if (i < N_NODES) g_deg[i] = 0;
}

__global__ void k_count(const int* __restrict__ edges) {
    int e = blockIdx.x * blockDim.x + threadIdx.x;
    if (e < NEDGE) atomicAdd(&g_deg[edges[2 * e]], 1);
}

// Single-block exclusive scan of degrees -> CSR row offsets (+ cursors, dinv).
// N = 12288 = 1024 * 12 exactly.
__global__ void k_scan() {
    __shared__ int sums[1024];
    const int PER = N_NODES / 1024;   // 12
    int t = threadIdx.x;
    int base = t * PER;
    int loc[PER];
    int s = 0;
#pragma unroll
    for (int q = 0; q < PER; q++) { loc[q] = s; s += g_deg[base + q]; }
    sums[t] = s;
    __syncthreads();
    // Hillis-Steele inclusive scan over the 1024 per-thread totals.
    for (int d = 1; d < 1024; d <<= 1) {
        int v = (t >= d) ? sums[t - d] : 0;
        __syncthreads();
        if (t >= d) sums[t] += v;
        __syncthreads();
    }
    int excl = sums[t] - s;
#pragma unroll
    for (int q = 0; q < PER; q++) {
        int o = excl + loc[q];
        g_off[base + q] = o;
        g_pos[base + q] = o;
        g_dinv[base + q] = rsqrtf((float)g_deg[base + q]);
    }
    if (t == 1023) g_off[N_NODES] = sums[1023];
}

__global__ void k_scatter(const int* __restrict__ edges) {
    int e = blockIdx.x * blockDim.x + threadIdx.x;
    if (e < NEDGE) {
        int r = edges[2 * e];
        int c = edges[2 * e + 1];
        int idx = atomicAdd(&g_pos[r], 1);
        g_col[idx] = c;
    }
}

// --------------------------------------------------- P = emb@W1 + b1 -------
// 256 threads / block, 16 rows / block, each thread owns 2 output columns.
// W1 staged in smem (32 KB); emb rows read as float4 (broadcast within warp).
__global__ void k_gemm0(const float* __restrict__ emb,
                        const float* __restrict__ W1,
                        const float* __restrict__ b1) {
    __shared__ float W1s[EMBD * FEAT];   // 32 KB
    int t = threadIdx.x;
    {
        const float4* src = (const float4*)W1;
        float4*       dst = (float4*)W1s;
#pragma unroll
        for (int q = 0; q < (EMBD * FEAT / 4) / 256; q++)   // 8 iters
            dst[t + q * 256] = src[t + q * 256];
    }
    __syncthreads();

    int rloc = t >> 4;            // 0..15
    int c0   = (t & 15) * 2;      // even column
    int r    = blockIdx.x * 16 + rloc;
    if (r >= VOCAB) return;

    float a0 = b1[c0];
    float a1 = b1[c0 + 1];
    const float4* e4 = (const float4*)(emb + (size_t)r * EMBD);
#pragma unroll 8
    for (int k4 = 0; k4 < EMBD / 4; k4++) {
        float4 f = e4[k4];
        const float fv[4] = {f.x, f.y, f.z, f.w};
#pragma unroll
        for (int j = 0; j < 4; j++) {
            int k = k4 * 4 + j;
            float2 w = *(const float2*)&W1s[k * FEAT + c0];
            a0 = fmaf(fv[j], w.x, a0);
            a1 = fmaf(fv[j], w.y, a1);
        }
    }
    g_P[r * FEAT + c0]     = a0;
    g_P[r * FEAT + c0 + 1] = a1;
}

// ------------------------- layer 1: h = relu(An @ X1); X2 = h@W2 + b2 ------
// One warp per node row; lane = feature column. h stays in registers;
// the 32x32 GEMM2 is done with shuffles against smem-resident W2.
__global__ void k_layer1(const int* __restrict__ nid,
                         const float* __restrict__ W2,
                         const float* __restrict__ b2) {
    __shared__ float W2s[FEAT * FEAT];   // 4 KB
    int t = threadIdx.x;
    ((float4*)W2s)[t] = ((const float4*)W2)[t];   // 256 threads x 16B = 4 KB
    __syncthreads();

    int lane = t & 31;
    int i = blockIdx.x * 8 + (t >> 5);
    int s   = g_off[i];
    int end = g_off[i + 1];
    float acc = 0.f;
    for (int idx = s; idx < end; idx++) {
        int j = g_col[idx];
        acc = fmaf(g_dinv[j], g_P[nid[j] * FEAT + lane], acc);
    }
    float h = fmaxf(g_dinv[i] * acc, 0.f);

    float x2 = b2[lane];
#pragma unroll
    for (int k = 0; k < FEAT; k++) {
        float hk = __shfl_sync(0xffffffffu, h, k);
        x2 = fmaf(hk, W2s[k * FEAT + lane], x2);
    }
    g_X2[i * FEAT + lane] = x2;
}

// ------------------------------- layer 2: out = relu(An @ X2) --------------
__global__ void k_layer2(float* __restrict__ out) {
    int t = threadIdx.x;
    int lane = t & 31;
    int i = blockIdx.x * 8 + (t >> 5);
    int s   = g_off[i];
    int end = g_off[i + 1];
    float acc = 0.f;
    for (int idx = s; idx < end; idx++) {
        int j = g_col[idx];
        acc = fmaf(g_dinv[j], g_X2[j * FEAT + lane], acc);
    }
    out[i * FEAT + lane] = fmaxf(g_dinv[i] * acc, 0.f);
}

// ---------------------------------------------------------------------------
extern "C" void kernel_launch(void* const* d_in, const int* in_sizes, int n_in,
                              void* d_out, int out_size) {
    const int*   node_ids = (const int*)d_in[0];
    const int*   edges    = (const int*)d_in[1];
    const float* emb      = (const float*)d_in[2];
    const float* W1       = (const float*)d_in[3];
    const float* b1       = (const float*)d_in[4];
    const float* W2       = (const float*)d_in[5];
    const float* b2       = (const float*)d_in[6];
    float* out = (float*)d_out;

    k_zero_deg<<<(N_NODES + 255) / 256, 256>>>();
    k_count<<<(NEDGE + 255) / 256, 256>>>(edges);
    k_scan<<<1, 1024>>>();
    k_scatter<<<(NEDGE + 255) / 256, 256>>>(edges);
    k_gemm0<<<(VOCAB + 15) / 16, 256>>>(emb, W1, b1);
    k_layer1<<<N_NODES / 8, 256>>>(node_ids, W2, b2);
    k_layer2<<<N_NODES / 8, 256>>>(out);
}

// round 2
// speedup vs baseline: 1.3683x; 1.3683x over previous
#include <cuda_runtime.h>

// ---------------------------------------------------------------------------
// SLUGenNet GCN, fully fused into ONE persistent kernel with software grid
// barriers (monotonic generation counter -> no reset races across graph
// replays).
//
//   P  = embed_table @ W1 + b1            (vocab-side: V=1000 rows, not N)
//   h  = relu(An @ P[node_ids]) ; X2 = h @ W2 + b2   (GEMM2 via shuffles)
//   out= relu(An @ X2)
//
// An is CSR-built in-kernel: degree count -> hierarchical scan -> scatter.
// g_deg is re-zeroed in the scan phase (so no zero-kernel and module-load
// zero-init makes the first run correct).
// ---------------------------------------------------------------------------

#define N_NODES 12288
#define VOCAB   1000
#define EMBD    256
#define FEAT    32
#define NEDGE   (2 * N_NODES - 1)

#define GRID     128
#define NTHREADS 512
#define NWARPS   (NTHREADS / 32)          // 16
#define TOTWARPS (GRID * NWARPS)          // 2048
#define CHUNK    (N_NODES / GRID)         // 96

// Scratch (__device__ globals; allocation-free rule)
__device__ int   g_deg[N_NODES];          // zero-init at load; re-zeroed per run
__device__ int   g_off[N_NODES + 1];
__device__ int   g_pos[N_NODES];
__device__ int   g_col[NEDGE];
__device__ float g_dinv[N_NODES];
__device__ float g_P[VOCAB * FEAT];
__device__ float g_X2[N_NODES * FEAT];
__device__ int   g_bsum[GRID];

// Grid barrier state: monotonic, never reset.
__device__ unsigned g_arrive;
__device__ volatile unsigned g_release;

__device__ __forceinline__ void gsync(unsigned gen) {
    __syncthreads();
    if (threadIdx.x == 0) {
        __threadfence();
        unsigned a = atomicAdd(&g_arrive, 1u) + 1u;
        if (a == gen * (unsigned)GRID) {
            g_release = gen;
        } else {
            while (g_release < gen) { }
        }
        __threadfence();
    }
    __syncthreads();
}

__device__ __forceinline__ int warp_incl_scan(int v, unsigned lane) {
#pragma unroll
    for (int d = 1; d < 32; d <<= 1) {
        int t = __shfl_up_sync(0xffffffffu, v, d);
        if (lane >= d) v += t;
    }
    return v;
}

__global__ __launch_bounds__(NTHREADS, 1)
void slu_fused(const int*   __restrict__ nid,
               const int*   __restrict__ edges,
               const float* __restrict__ emb,
               const float* __restrict__ W1,
               const float* __restrict__ b1,
               const float* __restrict__ W2,
               const float* __restrict__ b2,
               float*       __restrict__ out) {
    __shared__ float s_buf[EMBD * FEAT];  // 32 KB: W1 tile, later W2 (4 KB)
    __shared__ int   s_ws[4];             // warp totals (chunk scan, <=3 warps used)
    __shared__ int   s_ws2[4];            // warp totals (block-partials scan)
    __shared__ int   s_bsum[GRID];
    __shared__ int   s_bb;                // this block's global CSR base

    const int      t    = threadIdx.x;
    const unsigned lane = t & 31u;
    const int      warp = t >> 5;
    const int      b    = blockIdx.x;
    const int      gtid = b * NTHREADS + t;

    const unsigned base = g_release;      // stable since previous launch ended

    // ---- phase 1: degree count ------------------------------------------
    const int2* e2 = (const int2*)edges;
    if (gtid < NEDGE) atomicAdd(&g_deg[e2[gtid].x], 1);

    gsync(base + 1);

    // ---- phase 2a: per-block partial degree sums ------------------------
    const int chunk0 = b * CHUNK;
    int v = 0, incl = 0;
    if (t < CHUNK) {                      // 3 full warps (CHUNK = 96)
        v = g_deg[chunk0 + t];
        incl = warp_incl_scan(v, lane);
        if (lane == 31) s_ws[warp] = incl;
    }
    __syncthreads();
    if (t == 0) {
        int tot = 0;
#pragma unroll
        for (int w = 0; w < CHUNK / 32; w++) tot += s_ws[w];
        g_bsum[b] = tot;
    }

    gsync(base + 2);

    // ---- phase 2b: every block scans the GRID partials + local scan -----
    if (t < GRID) {                       // 4 full warps (GRID = 128)
        int bv   = g_bsum[t];
        int binc = warp_incl_scan(bv, lane);
        if (lane == 31) s_ws2[warp] = binc;
        s_bsum[t] = binc - bv;            // warp-local exclusive
    }
    __syncthreads();
    if (t == b) {                         // the thread matching our block id
        int off = s_bsum[t];
        for (int w = 0; w < (t >> 5); w++) off += s_ws2[w];
        s_bb = off;
    }
    __syncthreads();
    if (t < CHUNK) {
        int woff = 0;
        for (int w = 0; w < warp; w++) woff += s_ws[w];
        int excl = s_bb + woff + incl - v;
        int node = chunk0 + t;
        g_off[node]  = excl;
        g_pos[node]  = excl;
        g_dinv[node] = rsqrtf((float)v);
        g_deg[node]  = 0;                 // reset for next launch
    }
    if (b == 0 && t == 0) g_off[N_NODES] = NEDGE;  // total degree == #edges

    gsync(base + 3);

    // ---- phase 3: CSR scatter + GEMM0 (independent work) ----------------
    if (gtid < NEDGE) {
        int2 pc = e2[gtid];
        int idx = atomicAdd(&g_pos[pc.x], 1);
        g_col[idx] = pc.y;
    }

    // GEMM0: P = emb @ W1 + b1  (V x 256 x 32). W1 staged in smem.
    {
        const float4* src = (const float4*)W1;
        float4*       dst = (float4*)s_buf;
#pragma unroll
        for (int q = 0; q < (EMBD * FEAT / 4) / NTHREADS; q++)  // 4 iters
            dst[t + q * NTHREADS] = src[t + q * NTHREADS];
        __syncthreads();

        int rloc = t >> 4;                // 0..31 (32 rows / block)
        int c0   = (t & 15) * 2;
        int r    = b * (NTHREADS / 16) + rloc;
        if (r < VOCAB) {
            float a0 = b1[c0];
            float a1 = b1[c0 + 1];
            const float4* erow = (const float4*)(emb + (size_t)r * EMBD);
#pragma unroll 8
            for (int k4 = 0; k4 < EMBD / 4; k4++) {
                float4 f = erow[k4];
                const float fv[4] = {f.x, f.y, f.z, f.w};
#pragma unroll
                for (int j = 0; j < 4; j++) {
                    int k = k4 * 4 + j;
                    float2 w = *(const float2*)&s_buf[k * FEAT + c0];
                    a0 = fmaf(fv[j], w.x, a0);
                    a1 = fmaf(fv[j], w.y, a1);
                }
            }
            g_P[r * FEAT + c0]     = a0;
            g_P[r * FEAT + c0 + 1] = a1;
        }
    }

    gsync(base + 4);

    // ---- phase 4: h = relu(An @ P[nid]);  X2 = h @ W2 + b2 --------------
    {
        // stage W2 (4 KB) into s_buf
        if (t < FEAT * FEAT / 4)
            ((float4*)s_buf)[t] = ((const float4*)W2)[t];
        __syncthreads();

        const int   gw  = b * NWARPS + warp;
        const float b2v = b2[lane];
#pragma unroll
        for (int i = gw; i < N_NODES; i += TOTWARPS) {   // 6 rows / warp
            int s = g_off[i], e = g_off[i + 1];
            float acc = 0.f;
            for (int idx = s; idx < e; idx++) {
                int j = g_col[idx];
                acc = fmaf(g_dinv[j], g_P[nid[j] * FEAT + lane], acc);
            }
            float h  = fmaxf(g_dinv[i] * acc, 0.f);
            float x2 = b2v;
#pragma unroll
            for (int k = 0; k < FEAT; k++) {
                float hk = __shfl_sync(0xffffffffu, h, k);
                x2 = fmaf(hk, s_buf[k * FEAT + lane], x2);
            }
            g_X2[i * FEAT + lane] = x2;
        }
    }

    gsync(base + 5);

    // ---- phase 5: out = relu(An @ X2) -----------------------------------
    {
        const int gw = b * NWARPS + warp;
#pragma unroll
        for (int i = gw; i < N_NODES; i += TOTWARPS) {
            int s = g_off[i], e = g_off[i + 1];
            float acc = 0.f;
            for (int idx = s; idx < e; idx++) {
                int j = g_col[idx];
                acc = fmaf(g_dinv[j], g_X2[j * FEAT + lane], acc);
            }
            out[i * FEAT + lane] = fmaxf(g_dinv[i] * acc, 0.f);
        }
    }
}

// ---------------------------------------------------------------------------
extern "C" void kernel_launch(void* const* d_in, const int* in_sizes, int n_in,
                              void* d_out, int out_size) {
    const int*   node_ids = (const int*)d_in[0];
    const int*   edges    = (const int*)d_in[1];
    const float* emb      = (const float*)d_in[2];
    const float* W1       = (const float*)d_in[3];
    const float* b1       = (const float*)d_in[4];
    const float* W2       = (const float*)d_in[5];
    const float* b2       = (const float*)d_in[6];
    float* out = (float*)d_out;

    slu_fused<<<GRID, NTHREADS>>>(node_ids, edges, emb, W1, b1, W2, b2, out);
}